// round 1
// baseline (speedup 1.0000x reference)
#include <cuda_runtime.h>
#include <cstdint>

#define TKN 8192   // tokens = 4*2048
#define NF  4096   // in features
#define OF  4096   // out features

// Scratch (static device globals -- allocation-free per harness rules)
__device__ float g_x[(size_t)TKN * NF];   // 128 MB: fwht(input*SU)*scale, tf32-rounded
__device__ float g_w[(size_t)OF * NF];    //  64 MB: dequantized W, tf32-rounded
__device__ float g_y[(size_t)TKN * OF];   // 128 MB: GEMM output

__device__ __forceinline__ float tf32r(float f) {
    uint32_t u;
    asm("cvt.rna.tf32.f32 %0, %1;" : "=r"(u) : "f"(f));
    return __uint_as_float(u);
}

// ---------------------------------------------------------------------------
// Kernel 1: x' = tf32( fwht(input * SU) * Wscale/64 )
// One block per token row; 4096-float FWHT in shared memory, butterfly order
// identical to the reference (h = 1,2,...,2048).
// ---------------------------------------------------------------------------
__global__ __launch_bounds__(1024) void fwht_in_kernel(
        const float* __restrict__ in, const float* __restrict__ SU,
        const float* __restrict__ wscale) {
    __shared__ float s[4096];
    const int row = blockIdx.x;
    const int tid = threadIdx.x;

    float4 v = ((const float4*)(in + (size_t)row * NF))[tid];
    float4 u = ((const float4*)SU)[tid];
    s[tid*4+0] = v.x*u.x; s[tid*4+1] = v.y*u.y;
    s[tid*4+2] = v.z*u.z; s[tid*4+3] = v.w*u.w;

    for (int h = 1; h < 4096; h <<= 1) {
        __syncthreads();
        #pragma unroll
        for (int r = 0; r < 2; r++) {
            int p = tid + (r << 10);
            int i = ((p & ~(h-1)) << 1) | (p & (h-1));
            float a = s[i], b = s[i+h];
            s[i] = a + b; s[i+h] = a - b;
        }
    }
    __syncthreads();

    const float sc = wscale[0] * 0.015625f;   // Wscale / sqrt(4096)
    float4 o;
    o.x = tf32r(s[tid*4+0]*sc); o.y = tf32r(s[tid*4+1]*sc);
    o.z = tf32r(s[tid*4+2]*sc); o.w = tf32r(s[tid*4+3]*sc);
    ((float4*)(g_x + (size_t)row * NF))[tid] = o;
}

// ---------------------------------------------------------------------------
// Kernel 2: dequantize W[o][i] = tf32( cb[Qidxs[o][i/4]][i%4] )
// One thread per code (float4 of W).
// ---------------------------------------------------------------------------
__global__ __launch_bounds__(256) void dequant_kernel(
        const float* __restrict__ cb, const int* __restrict__ qidx) {
    int idx = blockIdx.x * 256 + threadIdx.x;   // 0 .. OF*NF/4-1
    int q = __ldg(qidx + idx);
    float4 v = __ldg((const float4*)cb + q);
    v.x = tf32r(v.x); v.y = tf32r(v.y); v.z = tf32r(v.z); v.w = tf32r(v.w);
    ((float4*)g_w)[idx] = v;
}

// ---------------------------------------------------------------------------
// Kernel 3: GEMM  g_y[t][o] = sum_i g_x[t][i] * g_w[o][i]
// tf32 mma.sync.m16n8k8, BM=256 BN=128 BK=32, 8 warps of 64x64 warptiles,
// cp.async double-buffered smem.
// ---------------------------------------------------------------------------
#define BM 256
#define BN 128
#define BK 32
#define PAD 36                       // smem row stride in floats (conflict-free frags)
#define KITERS (NF / BK)             // 128
#define A_BUF_FLOATS (BM * PAD)
#define B_BUF_FLOATS (BN * PAD)
#define SMEM_BYTES ((2 * (A_BUF_FLOATS + B_BUF_FLOATS)) * 4)   // 110592

__device__ __forceinline__ void cp16(float* dst, const float* src) {
    uint32_t d = (uint32_t)__cvta_generic_to_shared(dst);
    asm volatile("cp.async.cg.shared.global [%0], [%1], 16;" :: "r"(d), "l"(src));
}

__global__ __launch_bounds__(256, 1) void gemm_tf32_kernel() {
    extern __shared__ float sm[];
    float* As = sm;                          // [2][BM][PAD]
    float* Bs = sm + 2 * A_BUF_FLOATS;       // [2][BN][PAD]

    const int tid  = threadIdx.x;
    const int warp = tid >> 5, lane = tid & 31;
    const int wm = warp >> 1, wn = warp & 1;       // 4 x 2 warp grid
    const int g  = lane >> 2, t = lane & 3;        // groupID, threadID_in_group
    const int mBase = blockIdx.y * BM;
    const int nBase = blockIdx.x * BN;

    const int lrow = tid >> 3;         // 0..31
    const int lcol = (tid & 7) << 2;   // 0..28 step 4

    float acc[4][8][4];
    #pragma unroll
    for (int a = 0; a < 4; a++)
        #pragma unroll
        for (int b = 0; b < 8; b++)
            #pragma unroll
            for (int c = 0; c < 4; c++) acc[a][b][c] = 0.f;

    auto load_tile = [&](int buf, int kk) {
        const float* Ag = g_x + (size_t)(mBase + lrow) * NF + kk * BK + lcol;
        float* Ad = As + buf * A_BUF_FLOATS + lrow * PAD + lcol;
        #pragma unroll
        for (int p = 0; p < 8; p++)           // 8*32 = 256 rows
            cp16(Ad + p * 32 * PAD, Ag + (size_t)p * 32 * NF);
        const float* Bg = g_w + (size_t)(nBase + lrow) * NF + kk * BK + lcol;
        float* Bd = Bs + buf * B_BUF_FLOATS + lrow * PAD + lcol;
        #pragma unroll
        for (int p = 0; p < 4; p++)           // 4*32 = 128 rows
            cp16(Bd + p * 32 * PAD, Bg + (size_t)p * 32 * NF);
    };

    load_tile(0, 0);
    asm volatile("cp.async.commit_group;");

    int buf = 0;
    for (int kk = 0; kk < KITERS; kk++) {
        if (kk + 1 < KITERS) {
            load_tile(buf ^ 1, kk + 1);
            asm volatile("cp.async.commit_group;");
            asm volatile("cp.async.wait_group 1;");
        } else {
            asm volatile("cp.async.wait_group 0;");
        }
        __syncthreads();

        const float* Ab = As + buf * A_BUF_FLOATS + (wm * 64 + g) * PAD;
        const float* Bb = Bs + buf * B_BUF_FLOATS + (wn * 64 + g) * PAD;
        #pragma unroll
        for (int ks = 0; ks < 4; ks++) {
            const int k0 = ks * 8 + t;
            uint32_t af[4][4];
            #pragma unroll
            for (int mt = 0; mt < 4; mt++) {
                const float* p = Ab + mt * 16 * PAD + k0;
                af[mt][0] = __float_as_uint(p[0]);
                af[mt][1] = __float_as_uint(p[8 * PAD]);
                af[mt][2] = __float_as_uint(p[4]);
                af[mt][3] = __float_as_uint(p[8 * PAD + 4]);
            }
            uint32_t bf[8][2];
            #pragma unroll
            for (int nt = 0; nt < 8; nt++) {
                const float* p = Bb + nt * 8 * PAD + k0;
                bf[nt][0] = __float_as_uint(p[0]);
                bf[nt][1] = __float_as_uint(p[4]);
            }
            #pragma unroll
            for (int mt = 0; mt < 4; mt++)
                #pragma unroll
                for (int nt = 0; nt < 8; nt++) {
                    float* c = acc[mt][nt];
                    asm volatile(
                        "mma.sync.aligned.m16n8k8.row.col.f32.tf32.tf32.f32 "
                        "{%0,%1,%2,%3}, {%4,%5,%6,%7}, {%8,%9}, {%0,%1,%2,%3};"
                        : "+f"(c[0]), "+f"(c[1]), "+f"(c[2]), "+f"(c[3])
                        : "r"(af[mt][0]), "r"(af[mt][1]), "r"(af[mt][2]), "r"(af[mt][3]),
                          "r"(bf[nt][0]), "r"(bf[nt][1]));
                }
        }
        __syncthreads();
        buf ^= 1;
    }

    // Epilogue: write accumulators to g_y
    #pragma unroll
    for (int mt = 0; mt < 4; mt++) {
        #pragma unroll
        for (int nt = 0; nt < 8; nt++) {
            int r0 = mBase + wm * 64 + mt * 16 + g;
            int c0 = nBase + wn * 64 + nt * 8 + (t << 1);
            *(float2*)(g_y + (size_t)r0 * OF + c0) =
                make_float2(acc[mt][nt][0], acc[mt][nt][1]);
            *(float2*)(g_y + (size_t)(r0 + 8) * OF + c0) =
                make_float2(acc[mt][nt][2], acc[mt][nt][3]);
        }
    }
}

// ---------------------------------------------------------------------------
// Kernel 4: out = fwht(g_y)/64 * SV + bias
// ---------------------------------------------------------------------------
__global__ __launch_bounds__(1024) void fwht_out_kernel(
        const float* __restrict__ SV, const float* __restrict__ bias,
        float* __restrict__ out) {
    __shared__ float s[4096];
    const int row = blockIdx.x;
    const int tid = threadIdx.x;

    float4 v = ((const float4*)(g_y + (size_t)row * OF))[tid];
    s[tid*4+0] = v.x; s[tid*4+1] = v.y; s[tid*4+2] = v.z; s[tid*4+3] = v.w;

    for (int h = 1; h < 4096; h <<= 1) {
        __syncthreads();
        #pragma unroll
        for (int r = 0; r < 2; r++) {
            int p = tid + (r << 10);
            int i = ((p & ~(h-1)) << 1) | (p & (h-1));
            float a = s[i], b = s[i+h];
            s[i] = a + b; s[i+h] = a - b;
        }
    }
    __syncthreads();

    float4 sv = ((const float4*)SV)[tid];
    float4 bs = ((const float4*)bias)[tid];
    float4 o;
    o.x = s[tid*4+0] * 0.015625f * sv.x + bs.x;
    o.y = s[tid*4+1] * 0.015625f * sv.y + bs.y;
    o.z = s[tid*4+2] * 0.015625f * sv.z + bs.z;
    o.w = s[tid*4+3] * 0.015625f * sv.w + bs.w;
    ((float4*)(out + (size_t)row * OF))[tid] = o;
}

// ---------------------------------------------------------------------------
extern "C" void kernel_launch(void* const* d_in, const int* in_sizes, int n_in,
                              void* d_out, int out_size) {
    const float* input  = (const float*)d_in[0];
    const float* SU     = (const float*)d_in[1];
    const float* SV     = (const float*)d_in[2];
    const float* cb     = (const float*)d_in[3];
    const int*   Qidxs  = (const int*)d_in[4];
    const float* Wscale = (const float*)d_in[5];
    const float* bias   = (const float*)d_in[6];
    float* out = (float*)d_out;

    cudaFuncSetAttribute(gemm_tf32_kernel,
                         cudaFuncAttributeMaxDynamicSharedMemorySize, SMEM_BYTES);

    fwht_in_kernel<<<TKN, 1024>>>(input, SU, Wscale);
    dequant_kernel<<<(OF * (NF / 4)) / 256, 256>>>(cb, Qidxs);
    gemm_tf32_kernel<<<dim3(OF / BN, TKN / BM), 256, SMEM_BYTES>>>();
    fwht_out_kernel<<<TKN, 1024>>>(SV, bias, out);
}

// round 3
// speedup vs baseline: 1.9030x; 1.9030x over previous
#include <cuda_runtime.h>
#include <cuda_fp16.h>
#include <cstdint>

#define TKN 8192   // tokens = 4*2048
#define NF  4096   // in features
#define OF  4096   // out features

// Scratch (static device globals -- allocation-free per harness rules)
__device__ __half g_x[(size_t)TKN * NF];   // 64 MB: fwht(input*SU)*scale, fp16
__device__ __half g_w[(size_t)OF * NF];    // 32 MB: dequantized W, fp16
__device__ float  g_y[(size_t)TKN * OF];   // 128 MB: GEMM output (fp32)

// ---------------------------------------------------------------------------
// Kernel 1: g_x = fp16( fwht(input * SU) * Wscale/64 )
// ---------------------------------------------------------------------------
__global__ __launch_bounds__(1024) void fwht_in_kernel(
        const float* __restrict__ in, const float* __restrict__ SU,
        const float* __restrict__ wscale) {
    __shared__ float s[4096];
    const int row = blockIdx.x;
    const int tid = threadIdx.x;

    float4 v = ((const float4*)(in + (size_t)row * NF))[tid];
    float4 u = ((const float4*)SU)[tid];
    s[tid*4+0] = v.x*u.x; s[tid*4+1] = v.y*u.y;
    s[tid*4+2] = v.z*u.z; s[tid*4+3] = v.w*u.w;

    for (int h = 1; h < 4096; h <<= 1) {
        __syncthreads();
        #pragma unroll
        for (int r = 0; r < 2; r++) {
            int p = tid + (r << 10);
            int i = ((p & ~(h-1)) << 1) | (p & (h-1));
            float a = s[i], b = s[i+h];
            s[i] = a + b; s[i+h] = a - b;
        }
    }
    __syncthreads();

    const float sc = wscale[0] * 0.015625f;   // Wscale / sqrt(4096)
    __half2* dst = (__half2*)(g_x + (size_t)row * NF);
    dst[tid*2+0] = __floats2half2_rn(s[tid*4+0]*sc, s[tid*4+1]*sc);
    dst[tid*2+1] = __floats2half2_rn(s[tid*4+2]*sc, s[tid*4+3]*sc);
}

// ---------------------------------------------------------------------------
// Kernel 2: dequantize W -> fp16
// ---------------------------------------------------------------------------
__global__ __launch_bounds__(256) void dequant_kernel(
        const float* __restrict__ cb, const int* __restrict__ qidx) {
    int idx = blockIdx.x * 256 + threadIdx.x;   // 0 .. OF*NF/4-1
    int q = __ldg(qidx + idx);
    float4 v = __ldg((const float4*)cb + q);
    __half2 a = __floats2half2_rn(v.x, v.y);
    __half2 b = __floats2half2_rn(v.z, v.w);
    uint2 o;
    o.x = *reinterpret_cast<uint32_t*>(&a);
    o.y = *reinterpret_cast<uint32_t*>(&b);
    ((uint2*)g_w)[idx] = o;
}

// ---------------------------------------------------------------------------
// Kernel 3: fp16 mma.sync GEMM  g_y[t][o] = sum_i g_x[t][i] * g_w[o][i]
// BM=256 BN=128 BK=64(halves, 128B SW128 rows), 8 warps of 64x64,
// ldmatrix fragment loads, 3-stage cp.async pipeline.
// ---------------------------------------------------------------------------
#define BM 256
#define BN 128
#define BKH 64                       // halves per k-chunk (128 bytes)
#define STAGES 3
#define KITERS (NF / BKH)            // 64
#define A_TILE_B (BM * 128)          // 32768
#define B_TILE_B (BN * 128)          // 16384
#define STAGE_B  (A_TILE_B + B_TILE_B)      // 49152
#define GEMM_SMEM (STAGES * STAGE_B)        // 147456

__device__ __forceinline__ uint32_t sw128(uint32_t o) { return o ^ ((o >> 3) & 0x70); }

__device__ __forceinline__ void cpa(uint32_t dst, const void* src) {
    asm volatile("cp.async.cg.shared.global [%0], [%1], 16;" :: "r"(dst), "l"(src));
}

__device__ __forceinline__ void ldsm4(uint32_t* r, uint32_t addr) {
    asm volatile("ldmatrix.sync.aligned.m8n8.x4.shared.b16 {%0,%1,%2,%3}, [%4];"
                 : "=r"(r[0]), "=r"(r[1]), "=r"(r[2]), "=r"(r[3]) : "r"(addr));
}

__device__ __forceinline__ void load_stage(uint32_t base, int st, int mBase,
                                           int nBase, int tid) {
    const int k0 = st * BKH;
    const __half* A = g_x + (size_t)mBase * NF + k0;
    const __half* B = g_w + (size_t)nBase * NF + k0;
    #pragma unroll
    for (int i = 0; i < 8; i++) {                 // A: 2048 x 16B
        int id = tid + (i << 8);
        int r = id >> 3, c = id & 7;
        cpa(base + sw128(r * 128 + c * 16), A + (size_t)r * NF + c * 8);
    }
    #pragma unroll
    for (int i = 0; i < 4; i++) {                 // B: 1024 x 16B
        int id = tid + (i << 8);
        int r = id >> 3, c = id & 7;
        cpa(base + A_TILE_B + sw128(r * 128 + c * 16), B + (size_t)r * NF + c * 8);
    }
    asm volatile("cp.async.commit_group;");
}

__global__ __launch_bounds__(256, 1) void gemm_f16_kernel() {
    extern __shared__ __align__(1024) uint8_t sm[];
    const uint32_t smem_base = (uint32_t)__cvta_generic_to_shared(sm);

    const int tid  = threadIdx.x;
    const int warp = tid >> 5, lane = tid & 31;
    const int wm = warp >> 1, wn = warp & 1;       // 4 x 2 warp grid, 64x64 tiles
    const int g  = lane >> 2, t = lane & 3;
    const int mBase = blockIdx.y * BM;
    const int nBase = blockIdx.x * BN;

    // ldmatrix lane addressing components
    const int a_row  = lane & 15;                  // row within 16-row tile
    const int a_koff = (lane >> 4) * 16;           // 0 or 16 bytes (k 0-7 / 8-15)
    const int b_row  = (lane & 7) + ((lane >> 4) & 1) * 8;   // n within 16
    const int b_koff = ((lane >> 3) & 1) * 16;     // 0 or 16 bytes

    float acc[4][8][4];
    #pragma unroll
    for (int a = 0; a < 4; a++)
        #pragma unroll
        for (int b = 0; b < 8; b++)
            #pragma unroll
            for (int c = 0; c < 4; c++) acc[a][b][c] = 0.f;

    load_stage(smem_base + 0 * STAGE_B, 0, mBase, nBase, tid);
    load_stage(smem_base + 1 * STAGE_B, 1, mBase, nBase, tid);

    for (int s = 0; s < KITERS; s++) {
        if (s < KITERS - 1) asm volatile("cp.async.wait_group 1;" ::: "memory");
        else                asm volatile("cp.async.wait_group 0;" ::: "memory");
        __syncthreads();

        if (s + 2 < KITERS)
            load_stage(smem_base + ((s + 2) % STAGES) * STAGE_B, s + 2,
                       mBase, nBase, tid);

        const uint32_t As = smem_base + (s % STAGES) * STAGE_B;
        const uint32_t Bs = As + A_TILE_B;

        #pragma unroll
        for (int kc = 0; kc < 4; kc++) {           // 4 k-chunks of 16
            uint32_t af[4][4];
            #pragma unroll
            for (int mt = 0; mt < 4; mt++)
                ldsm4(af[mt], As + sw128((wm * 64 + mt * 16 + a_row) * 128 +
                                          kc * 32 + a_koff));
            uint32_t bf[4][4];                     // [np][tile0 b0,b1, tile1 b0,b1]
            #pragma unroll
            for (int np = 0; np < 4; np++)
                ldsm4(bf[np], Bs + sw128((wn * 64 + np * 16 + b_row) * 128 +
                                          kc * 32 + b_koff));
            #pragma unroll
            for (int mt = 0; mt < 4; mt++)
                #pragma unroll
                for (int nt = 0; nt < 8; nt++) {
                    float* c = acc[mt][nt];
                    const uint32_t b0 = bf[nt >> 1][(nt & 1) * 2 + 0];
                    const uint32_t b1 = bf[nt >> 1][(nt & 1) * 2 + 1];
                    asm volatile(
                        "mma.sync.aligned.m16n8k16.row.col.f32.f16.f16.f32 "
                        "{%0,%1,%2,%3}, {%4,%5,%6,%7}, {%8,%9}, {%0,%1,%2,%3};"
                        : "+f"(c[0]), "+f"(c[1]), "+f"(c[2]), "+f"(c[3])
                        : "r"(af[mt][0]), "r"(af[mt][1]),
                          "r"(af[mt][2]), "r"(af[mt][3]),
                          "r"(b0), "r"(b1));
                }
        }
        __syncthreads();
    }

    // Epilogue: write accumulators to g_y
    #pragma unroll
    for (int mt = 0; mt < 4; mt++) {
        #pragma unroll
        for (int nt = 0; nt < 8; nt++) {
            int r0 = mBase + wm * 64 + mt * 16 + g;
            int c0 = nBase + wn * 64 + nt * 8 + (t << 1);
            *(float2*)(g_y + (size_t)r0 * OF + c0) =
                make_float2(acc[mt][nt][0], acc[mt][nt][1]);
            *(float2*)(g_y + (size_t)(r0 + 8) * OF + c0) =
                make_float2(acc[mt][nt][2], acc[mt][nt][3]);
        }
    }
}

// ---------------------------------------------------------------------------
// Kernel 4: out = fwht(g_y)/64 * SV + bias
// ---------------------------------------------------------------------------
__global__ __launch_bounds__(1024) void fwht_out_kernel(
        const float* __restrict__ SV, const float* __restrict__ bias,
        float* __restrict__ out) {
    __shared__ float s[4096];
    const int row = blockIdx.x;
    const int tid = threadIdx.x;

    float4 v = ((const float4*)(g_y + (size_t)row * OF))[tid];
    s[tid*4+0] = v.x; s[tid*4+1] = v.y; s[tid*4+2] = v.z; s[tid*4+3] = v.w;

    for (int h = 1; h < 4096; h <<= 1) {
        __syncthreads();
        #pragma unroll
        for (int r = 0; r < 2; r++) {
            int p = tid + (r << 10);
            int i = ((p & ~(h-1)) << 1) | (p & (h-1));
            float a = s[i], b = s[i+h];
            s[i] = a + b; s[i+h] = a - b;
        }
    }
    __syncthreads();

    float4 sv = ((const float4*)SV)[tid];
    float4 bs = ((const float4*)bias)[tid];
    float4 o;
    o.x = s[tid*4+0] * 0.015625f * sv.x + bs.x;
    o.y = s[tid*4+1] * 0.015625f * sv.y + bs.y;
    o.z = s[tid*4+2] * 0.015625f * sv.z + bs.z;
    o.w = s[tid*4+3] * 0.015625f * sv.w + bs.w;
    ((float4*)(out + (size_t)row * OF))[tid] = o;
}

// ---------------------------------------------------------------------------
extern "C" void kernel_launch(void* const* d_in, const int* in_sizes, int n_in,
                              void* d_out, int out_size) {
    const float* input  = (const float*)d_in[0];
    const float* SU     = (const float*)d_in[1];
    const float* SV     = (const float*)d_in[2];
    const float* cb     = (const float*)d_in[3];
    const int*   Qidxs  = (const int*)d_in[4];
    const float* Wscale = (const float*)d_in[5];
    const float* bias   = (const float*)d_in[6];
    float* out = (float*)d_out;

    cudaFuncSetAttribute(gemm_f16_kernel,
                         cudaFuncAttributeMaxDynamicSharedMemorySize, GEMM_SMEM);

    fwht_in_kernel<<<TKN, 1024>>>(input, SU, Wscale);
    dequant_kernel<<<(OF * (NF / 4)) / 256, 256>>>(cb, Qidxs);
    gemm_f16_kernel<<<dim3(OF / BN, TKN / BM), 256, GEMM_SMEM>>>();
    fwht_out_kernel<<<TKN, 1024>>>(SV, bias, out);
}

// round 4
// speedup vs baseline: 2.2445x; 1.1794x over previous
#include <cuda_runtime.h>
#include <cuda_fp16.h>
#include <cstdint>

#define TKN 8192   // tokens = 4*2048
#define NF  4096   // in features
#define OF  4096   // out features

// Scratch (static device globals -- allocation-free per harness rules)
__device__ __half g_x[(size_t)TKN * NF];   // 64 MB: fwht(input*SU)*scale, fp16
__device__ __half g_w[(size_t)OF * NF];    // 32 MB: dequantized W, fp16
__device__ float  g_y[(size_t)TKN * OF];   // 128 MB: GEMM output (fp32)

// ---------------------------------------------------------------------------
// Register/shuffle FWHT core: 256 threads, 16 elements/thread, N=4096.
// Stage partition (stages on distinct bits commute):
//   bits 0-3  : in-register (i = tid*16 + r)
//   bits 4-8  : warp shuffles (lane distance 1..16)
//   transpose : smem, regs become bits 8-11 (i = r*256 + tid)
//   bits 9-11 : in-register
// After the call, thread `tid` holds element i = r*256 + tid in v[r].
// ---------------------------------------------------------------------------
__device__ __forceinline__ void fwht4096(float* v, float* s, int tid) {
    const int lane = tid & 31;
    // bits 0-3
    #pragma unroll
    for (int h = 1; h < 16; h <<= 1)
        #pragma unroll
        for (int i = 0; i < 16; i++)
            if (!(i & h)) {
                float a = v[i], b = v[i ^ h];
                v[i] = a + b; v[i ^ h] = a - b;
            }
    // bits 4-8 (lane bits)
    #pragma unroll
    for (int d = 1; d < 32; d <<= 1) {
        #pragma unroll
        for (int r = 0; r < 16; r++) {
            float o = __shfl_xor_sync(0xffffffffu, v[r], d);
            v[r] = (lane & d) ? (o - v[r]) : (v[r] + o);
        }
    }
    // transpose through smem: write i = tid*16+r, read i = r*256+tid
    float4* sv = (float4*)(s + tid * 16);
    sv[0] = make_float4(v[0], v[1], v[2], v[3]);
    sv[1] = make_float4(v[4], v[5], v[6], v[7]);
    sv[2] = make_float4(v[8], v[9], v[10], v[11]);
    sv[3] = make_float4(v[12], v[13], v[14], v[15]);
    __syncthreads();
    #pragma unroll
    for (int r = 0; r < 16; r++) v[r] = s[r * 256 + tid];
    // bits 9-11 (r-distance 2,4,8)
    #pragma unroll
    for (int h = 2; h < 16; h <<= 1)
        #pragma unroll
        for (int i = 0; i < 16; i++)
            if (!(i & h)) {
                float a = v[i], b = v[i ^ h];
                v[i] = a + b; v[i ^ h] = a - b;
            }
}

// ---------------------------------------------------------------------------
// Kernel 1: g_x = fp16( fwht(input * SU) * Wscale/64 )
// ---------------------------------------------------------------------------
__global__ __launch_bounds__(256) void fwht_in_kernel(
        const float* __restrict__ in, const float* __restrict__ SU,
        const float* __restrict__ wscale) {
    __shared__ float s[4096];
    const int row = blockIdx.x;
    const int tid = threadIdx.x;

    float v[16];
    const float4* ip = (const float4*)(in + (size_t)row * NF + tid * 16);
    const float4* up = (const float4*)(SU + tid * 16);
    #pragma unroll
    for (int q = 0; q < 4; q++) {
        float4 a = ip[q], b = up[q];
        v[q*4+0] = a.x*b.x; v[q*4+1] = a.y*b.y;
        v[q*4+2] = a.z*b.z; v[q*4+3] = a.w*b.w;
    }

    fwht4096(v, s, tid);

    const float sc = wscale[0] * 0.015625f;   // Wscale / sqrt(4096)
    __half* dst = g_x + (size_t)row * NF + tid;
    #pragma unroll
    for (int r = 0; r < 16; r++)
        dst[r * 256] = __float2half_rn(v[r] * sc);
}

// ---------------------------------------------------------------------------
// Kernel 2: dequantize W -> fp16
// ---------------------------------------------------------------------------
__global__ __launch_bounds__(256) void dequant_kernel(
        const float* __restrict__ cb, const int* __restrict__ qidx) {
    int idx = blockIdx.x * 256 + threadIdx.x;   // 0 .. OF*NF/4-1
    int q = __ldg(qidx + idx);
    float4 v = __ldg((const float4*)cb + q);
    __half2 a = __floats2half2_rn(v.x, v.y);
    __half2 b = __floats2half2_rn(v.z, v.w);
    uint2 o;
    o.x = *reinterpret_cast<uint32_t*>(&a);
    o.y = *reinterpret_cast<uint32_t*>(&b);
    ((uint2*)g_w)[idx] = o;
}

// ---------------------------------------------------------------------------
// Kernel 3: fp16 mma.sync GEMM  g_y[t][o] = sum_i g_x[t][i] * g_w[o][i]
// BM=256 BN=128 BK=64(halves, 128B SW128 rows), 8 warps of 64x64,
// ldmatrix fragment loads, 3-stage cp.async pipeline.
// ---------------------------------------------------------------------------
#define BM 256
#define BN 128
#define BKH 64                       // halves per k-chunk (128 bytes)
#define STAGES 3
#define KITERS (NF / BKH)            // 64
#define A_TILE_B (BM * 128)          // 32768
#define B_TILE_B (BN * 128)          // 16384
#define STAGE_B  (A_TILE_B + B_TILE_B)      // 49152
#define GEMM_SMEM (STAGES * STAGE_B)        // 147456

__device__ __forceinline__ uint32_t sw128(uint32_t o) { return o ^ ((o >> 3) & 0x70); }

__device__ __forceinline__ void cpa(uint32_t dst, const void* src) {
    asm volatile("cp.async.cg.shared.global [%0], [%1], 16;" :: "r"(dst), "l"(src));
}

__device__ __forceinline__ void ldsm4(uint32_t* r, uint32_t addr) {
    asm volatile("ldmatrix.sync.aligned.m8n8.x4.shared.b16 {%0,%1,%2,%3}, [%4];"
                 : "=r"(r[0]), "=r"(r[1]), "=r"(r[2]), "=r"(r[3]) : "r"(addr));
}

__device__ __forceinline__ void load_stage(uint32_t base, int st, int mBase,
                                           int nBase, int tid) {
    const int k0 = st * BKH;
    const __half* A = g_x + (size_t)mBase * NF + k0;
    const __half* B = g_w + (size_t)nBase * NF + k0;
    #pragma unroll
    for (int i = 0; i < 8; i++) {                 // A: 2048 x 16B
        int id = tid + (i << 8);
        int r = id >> 3, c = id & 7;
        cpa(base + sw128(r * 128 + c * 16), A + (size_t)r * NF + c * 8);
    }
    #pragma unroll
    for (int i = 0; i < 4; i++) {                 // B: 1024 x 16B
        int id = tid + (i << 8);
        int r = id >> 3, c = id & 7;
        cpa(base + A_TILE_B + sw128(r * 128 + c * 16), B + (size_t)r * NF + c * 8);
    }
    asm volatile("cp.async.commit_group;");
}

__global__ __launch_bounds__(256, 1) void gemm_f16_kernel() {
    extern __shared__ __align__(1024) uint8_t sm[];
    const uint32_t smem_base = (uint32_t)__cvta_generic_to_shared(sm);

    const int tid  = threadIdx.x;
    const int warp = tid >> 5, lane = tid & 31;
    const int wm = warp >> 1, wn = warp & 1;       // 4 x 2 warp grid, 64x64 tiles
    const int g  = lane >> 2, t = lane & 3;
    const int mBase = blockIdx.y * BM;
    const int nBase = blockIdx.x * BN;

    // ldmatrix lane addressing components
    const int a_row  = lane & 15;                  // row within 16-row tile
    const int a_koff = (lane >> 4) * 16;           // 0 or 16 bytes (k 0-7 / 8-15)
    const int b_row  = (lane & 7) + ((lane >> 4) & 1) * 8;   // n within 16
    const int b_koff = ((lane >> 3) & 1) * 16;     // 0 or 16 bytes

    float acc[4][8][4];
    #pragma unroll
    for (int a = 0; a < 4; a++)
        #pragma unroll
        for (int b = 0; b < 8; b++)
            #pragma unroll
            for (int c = 0; c < 4; c++) acc[a][b][c] = 0.f;

    load_stage(smem_base + 0 * STAGE_B, 0, mBase, nBase, tid);
    load_stage(smem_base + 1 * STAGE_B, 1, mBase, nBase, tid);

    for (int s = 0; s < KITERS; s++) {
        if (s < KITERS - 1) asm volatile("cp.async.wait_group 1;" ::: "memory");
        else                asm volatile("cp.async.wait_group 0;" ::: "memory");
        __syncthreads();

        if (s + 2 < KITERS)
            load_stage(smem_base + ((s + 2) % STAGES) * STAGE_B, s + 2,
                       mBase, nBase, tid);

        const uint32_t As = smem_base + (s % STAGES) * STAGE_B;
        const uint32_t Bs = As + A_TILE_B;

        #pragma unroll
        for (int kc = 0; kc < 4; kc++) {           // 4 k-chunks of 16
            uint32_t af[4][4];
            #pragma unroll
            for (int mt = 0; mt < 4; mt++)
                ldsm4(af[mt], As + sw128((wm * 64 + mt * 16 + a_row) * 128 +
                                          kc * 32 + a_koff));
            uint32_t bf[4][4];                     // [np][tile0 b0,b1, tile1 b0,b1]
            #pragma unroll
            for (int np = 0; np < 4; np++)
                ldsm4(bf[np], Bs + sw128((wn * 64 + np * 16 + b_row) * 128 +
                                          kc * 32 + b_koff));
            #pragma unroll
            for (int mt = 0; mt < 4; mt++)
                #pragma unroll
                for (int nt = 0; nt < 8; nt++) {
                    float* c = acc[mt][nt];
                    const uint32_t b0 = bf[nt >> 1][(nt & 1) * 2 + 0];
                    const uint32_t b1 = bf[nt >> 1][(nt & 1) * 2 + 1];
                    asm volatile(
                        "mma.sync.aligned.m16n8k16.row.col.f32.f16.f16.f32 "
                        "{%0,%1,%2,%3}, {%4,%5,%6,%7}, {%8,%9}, {%0,%1,%2,%3};"
                        : "+f"(c[0]), "+f"(c[1]), "+f"(c[2]), "+f"(c[3])
                        : "r"(af[mt][0]), "r"(af[mt][1]),
                          "r"(af[mt][2]), "r"(af[mt][3]),
                          "r"(b0), "r"(b1));
                }
        }
        // NOTE: no trailing __syncthreads needed — the barrier at the top of
        // the next iteration separates these reads from the cp.async overwrite
        // of this buffer (which happens 3 stages later).
    }

    // Epilogue: write accumulators to g_y
    #pragma unroll
    for (int mt = 0; mt < 4; mt++) {
        #pragma unroll
        for (int nt = 0; nt < 8; nt++) {
            int r0 = mBase + wm * 64 + mt * 16 + g;
            int c0 = nBase + wn * 64 + nt * 8 + (t << 1);
            *(float2*)(g_y + (size_t)r0 * OF + c0) =
                make_float2(acc[mt][nt][0], acc[mt][nt][1]);
            *(float2*)(g_y + (size_t)(r0 + 8) * OF + c0) =
                make_float2(acc[mt][nt][2], acc[mt][nt][3]);
        }
    }
}

// ---------------------------------------------------------------------------
// Kernel 4: out = fwht(g_y)/64 * SV + bias
// ---------------------------------------------------------------------------
__global__ __launch_bounds__(256) void fwht_out_kernel(
        const float* __restrict__ SV, const float* __restrict__ bias,
        float* __restrict__ out) {
    __shared__ float s[4096];
    const int row = blockIdx.x;
    const int tid = threadIdx.x;

    float v[16];
    const float4* ip = (const float4*)(g_y + (size_t)row * OF + tid * 16);
    #pragma unroll
    for (int q = 0; q < 4; q++) {
        float4 a = ip[q];
        v[q*4+0] = a.x; v[q*4+1] = a.y; v[q*4+2] = a.z; v[q*4+3] = a.w;
    }

    fwht4096(v, s, tid);

    float* dst = out + (size_t)row * OF + tid;
    #pragma unroll
    for (int r = 0; r < 16; r++) {
        int c = r * 256 + tid;
        dst[r * 256] = v[r] * 0.015625f * SV[c] + bias[c];
    }
}

// ---------------------------------------------------------------------------
extern "C" void kernel_launch(void* const* d_in, const int* in_sizes, int n_in,
                              void* d_out, int out_size) {
    const float* input  = (const float*)d_in[0];
    const float* SU     = (const float*)d_in[1];
    const float* SV     = (const float*)d_in[2];
    const float* cb     = (const float*)d_in[3];
    const int*   Qidxs  = (const int*)d_in[4];
    const float* Wscale = (const float*)d_in[5];
    const float* bias   = (const float*)d_in[6];
    float* out = (float*)d_out;

    cudaFuncSetAttribute(gemm_f16_kernel,
                         cudaFuncAttributeMaxDynamicSharedMemorySize, GEMM_SMEM);

    fwht_in_kernel<<<TKN, 256>>>(input, SU, Wscale);
    dequant_kernel<<<(OF * (NF / 4)) / 256, 256>>>(cb, Qidxs);
    gemm_f16_kernel<<<dim3(OF / BN, TKN / BM), 256, GEMM_SMEM>>>();
    fwht_out_kernel<<<TKN, 256>>>(SV, bias, out);
}

// round 5
// speedup vs baseline: 2.3794x; 1.0601x over previous
#include <cuda_runtime.h>
#include <cuda_fp16.h>
#include <cstdint>

#define TKN 8192   // tokens = 4*2048
#define NF  4096   // in features
#define OF  4096   // out features

// Scratch (static device globals -- allocation-free per harness rules)
__device__ __half g_x[(size_t)TKN * NF];   // 64 MB: fwht(input*SU)*scale, fp16
__device__ __half g_w[(size_t)OF * NF];    // 32 MB: dequantized W, fp16
__device__ float  g_y[(size_t)TKN * OF];   // 128 MB: GEMM output (fp32)

// ---------------------------------------------------------------------------
// Register/shuffle FWHT core: 256 threads, 16 elements/thread, N=4096.
// ---------------------------------------------------------------------------
__device__ __forceinline__ void fwht4096(float* v, float* s, int tid) {
    const int lane = tid & 31;
    #pragma unroll
    for (int h = 1; h < 16; h <<= 1)
        #pragma unroll
        for (int i = 0; i < 16; i++)
            if (!(i & h)) {
                float a = v[i], b = v[i ^ h];
                v[i] = a + b; v[i ^ h] = a - b;
            }
    #pragma unroll
    for (int d = 1; d < 32; d <<= 1) {
        #pragma unroll
        for (int r = 0; r < 16; r++) {
            float o = __shfl_xor_sync(0xffffffffu, v[r], d);
            v[r] = (lane & d) ? (o - v[r]) : (v[r] + o);
        }
    }
    float4* sv = (float4*)(s + tid * 16);
    sv[0] = make_float4(v[0], v[1], v[2], v[3]);
    sv[1] = make_float4(v[4], v[5], v[6], v[7]);
    sv[2] = make_float4(v[8], v[9], v[10], v[11]);
    sv[3] = make_float4(v[12], v[13], v[14], v[15]);
    __syncthreads();
    #pragma unroll
    for (int r = 0; r < 16; r++) v[r] = s[r * 256 + tid];
    #pragma unroll
    for (int h = 2; h < 16; h <<= 1)
        #pragma unroll
        for (int i = 0; i < 16; i++)
            if (!(i & h)) {
                float a = v[i], b = v[i ^ h];
                v[i] = a + b; v[i ^ h] = a - b;
            }
}

// ---------------------------------------------------------------------------
// Kernel 1: g_x = fp16( fwht(input * SU) * Wscale/64 )
// ---------------------------------------------------------------------------
__global__ __launch_bounds__(256) void fwht_in_kernel(
        const float* __restrict__ in, const float* __restrict__ SU,
        const float* __restrict__ wscale) {
    __shared__ float s[4096];
    const int row = blockIdx.x;
    const int tid = threadIdx.x;

    float v[16];
    const float4* ip = (const float4*)(in + (size_t)row * NF + tid * 16);
    const float4* up = (const float4*)(SU + tid * 16);
    #pragma unroll
    for (int q = 0; q < 4; q++) {
        float4 a = ip[q], b = up[q];
        v[q*4+0] = a.x*b.x; v[q*4+1] = a.y*b.y;
        v[q*4+2] = a.z*b.z; v[q*4+3] = a.w*b.w;
    }

    fwht4096(v, s, tid);

    const float sc = wscale[0] * 0.015625f;   // Wscale / sqrt(4096)
    __half* dst = g_x + (size_t)row * NF + tid;
    #pragma unroll
    for (int r = 0; r < 16; r++)
        dst[r * 256] = __float2half_rn(v[r] * sc);
}

// ---------------------------------------------------------------------------
// Kernel 2: dequantize W -> fp16
// ---------------------------------------------------------------------------
__global__ __launch_bounds__(256) void dequant_kernel(
        const float* __restrict__ cb, const int* __restrict__ qidx) {
    int idx = blockIdx.x * 256 + threadIdx.x;   // 0 .. OF*NF/4-1
    int q = __ldg(qidx + idx);
    float4 v = __ldg((const float4*)cb + q);
    __half2 a = __floats2half2_rn(v.x, v.y);
    __half2 b = __floats2half2_rn(v.z, v.w);
    uint2 o;
    o.x = *reinterpret_cast<uint32_t*>(&a);
    o.y = *reinterpret_cast<uint32_t*>(&b);
    ((uint2*)g_w)[idx] = o;
}

// ---------------------------------------------------------------------------
// Kernel 3: fp16 mma.sync GEMM  g_y[t][o] = sum_i g_x[t][i] * g_w[o][i]
// BM=256 BN=128 BKH=128 (two stacked 128B SW128 sub-tiles per operand),
// 8 warps of 64x64, ldmatrix + fragment double-buffering,
// 2-stage cp.async pipeline (96KB/stage).
// ---------------------------------------------------------------------------
#define BM 256
#define BN 128
#define BKH 128                      // halves per k-stage (256 bytes, 2 sub-tiles)
#define KITERS (NF / BKH)            // 32
#define A_HALF_B (BM * 128)          // 32768
#define B_HALF_B (BN * 128)          // 16384
#define A_TILE_B (2 * A_HALF_B)      // 65536
#define B_TILE_B (2 * B_HALF_B)      // 32768
#define STAGE_B  (A_TILE_B + B_TILE_B)      // 98304
#define GEMM_SMEM (2 * STAGE_B)             // 196608

__device__ __forceinline__ uint32_t sw128(uint32_t o) { return o ^ ((o >> 3) & 0x70); }

__device__ __forceinline__ void cpa(uint32_t dst, const void* src) {
    asm volatile("cp.async.cg.shared.global [%0], [%1], 16;" :: "r"(dst), "l"(src));
}

__device__ __forceinline__ void ldsm4(uint32_t* r, uint32_t addr) {
    asm volatile("ldmatrix.sync.aligned.m8n8.x4.shared.b16 {%0,%1,%2,%3}, [%4];"
                 : "=r"(r[0]), "=r"(r[1]), "=r"(r[2]), "=r"(r[3]) : "r"(addr));
}

__device__ __forceinline__ void load_stage(uint32_t base, int st, int mBase,
                                           int nBase, int tid) {
    const int k0 = st * BKH;
    const __half* A = g_x + (size_t)mBase * NF + k0;
    const __half* B = g_w + (size_t)nBase * NF + k0;
    #pragma unroll
    for (int i = 0; i < 16; i++) {                // A: 4096 x 16B
        int id = tid + (i << 8);
        int r = id >> 4, c16 = id & 15;
        cpa(base + (c16 >> 3) * A_HALF_B + sw128(r * 128 + (c16 & 7) * 16),
            A + (size_t)r * NF + c16 * 8);
    }
    #pragma unroll
    for (int i = 0; i < 8; i++) {                 // B: 2048 x 16B
        int id = tid + (i << 8);
        int r = id >> 4, c16 = id & 15;
        cpa(base + A_TILE_B + (c16 >> 3) * B_HALF_B + sw128(r * 128 + (c16 & 7) * 16),
            B + (size_t)r * NF + c16 * 8);
    }
    asm volatile("cp.async.commit_group;");
}

__global__ __launch_bounds__(256, 1) void gemm_f16_kernel() {
    extern __shared__ __align__(1024) uint8_t sm[];
    const uint32_t smem_base = (uint32_t)__cvta_generic_to_shared(sm);

    const int tid  = threadIdx.x;
    const int warp = tid >> 5, lane = tid & 31;
    const int wm = warp >> 1, wn = warp & 1;       // 4 x 2 warp grid, 64x64 tiles
    const int g  = lane >> 2, t = lane & 3;
    const int mBase = blockIdx.y * BM;
    const int nBase = blockIdx.x * BN;

    // ldmatrix lane addressing
    const int a_row  = lane & 15;
    const int a_koff = (lane >> 4) * 16;           // 0/16 bytes
    const int b_row  = (lane & 7) + ((lane >> 4) & 1) * 8;
    const int b_koff = ((lane >> 3) & 1) * 16;

    // Precompute row base + swizzle XOR per fragment tile (low 7 bits of row
    // base are 0, so sw128(rowbase + koff) == rowbase + (koff ^ xorv)).
    uint32_t aBase[4], aXor[4], bBase[4], bXor[4];
    #pragma unroll
    for (int mt = 0; mt < 4; mt++) {
        uint32_t rb = (wm * 64 + mt * 16 + a_row) * 128;
        aBase[mt] = rb; aXor[mt] = (rb >> 3) & 0x70;
    }
    #pragma unroll
    for (int np = 0; np < 4; np++) {
        uint32_t rb = (wn * 64 + np * 16 + b_row) * 128;
        bBase[np] = rb; bXor[np] = (rb >> 3) & 0x70;
    }

    float acc[4][8][4];
    #pragma unroll
    for (int a = 0; a < 4; a++)
        #pragma unroll
        for (int b = 0; b < 8; b++)
            #pragma unroll
            for (int c = 0; c < 4; c++) acc[a][b][c] = 0.f;

    load_stage(smem_base, 0, mBase, nBase, tid);

    for (int s = 0; s < KITERS; s++) {
        asm volatile("cp.async.wait_group 0;" ::: "memory");
        __syncthreads();
        if (s + 1 < KITERS)
            load_stage(smem_base + ((s + 1) & 1) * STAGE_B, s + 1,
                       mBase, nBase, tid);

        const uint32_t As = smem_base + (s & 1) * STAGE_B;
        const uint32_t Bs = As + A_TILE_B;

        uint32_t af[2][4][4], bf[2][4][4];
        // prefetch kc = 0
        #pragma unroll
        for (int mt = 0; mt < 4; mt++)
            ldsm4(af[0][mt], As + aBase[mt] + (a_koff ^ aXor[mt]));
        #pragma unroll
        for (int np = 0; np < 4; np++)
            ldsm4(bf[0][np], Bs + bBase[np] + (b_koff ^ bXor[np]));

        #pragma unroll
        for (int kc = 0; kc < 8; kc++) {           // 8 k-chunks of 16
            const int cur = kc & 1, nxt = cur ^ 1;
            if (kc < 7) {
                const int kn = kc + 1;
                const uint32_t ah = As + (kn >> 2) * A_HALF_B;
                const uint32_t bh = Bs + (kn >> 2) * B_HALF_B;
                const uint32_t ak = (kn & 3) * 32 + a_koff;
                const uint32_t bk = (kn & 3) * 32 + b_koff;
                #pragma unroll
                for (int mt = 0; mt < 4; mt++)
                    ldsm4(af[nxt][mt], ah + aBase[mt] + (ak ^ aXor[mt]));
                #pragma unroll
                for (int np = 0; np < 4; np++)
                    ldsm4(bf[nxt][np], bh + bBase[np] + (bk ^ bXor[np]));
            }
            #pragma unroll
            for (int mt = 0; mt < 4; mt++)
                #pragma unroll
                for (int nt = 0; nt < 8; nt++) {
                    float* c = acc[mt][nt];
                    const uint32_t b0 = bf[cur][nt >> 1][(nt & 1) * 2 + 0];
                    const uint32_t b1 = bf[cur][nt >> 1][(nt & 1) * 2 + 1];
                    asm volatile(
                        "mma.sync.aligned.m16n8k16.row.col.f32.f16.f16.f32 "
                        "{%0,%1,%2,%3}, {%4,%5,%6,%7}, {%8,%9}, {%0,%1,%2,%3};"
                        : "+f"(c[0]), "+f"(c[1]), "+f"(c[2]), "+f"(c[3])
                        : "r"(af[cur][mt][0]), "r"(af[cur][mt][1]),
                          "r"(af[cur][mt][2]), "r"(af[cur][mt][3]),
                          "r"(b0), "r"(b1));
                }
        }
        __syncthreads();
    }

    // Epilogue: write accumulators to g_y
    #pragma unroll
    for (int mt = 0; mt < 4; mt++) {
        #pragma unroll
        for (int nt = 0; nt < 8; nt++) {
            int r0 = mBase + wm * 64 + mt * 16 + g;
            int c0 = nBase + wn * 64 + nt * 8 + (t << 1);
            *(float2*)(g_y + (size_t)r0 * OF + c0) =
                make_float2(acc[mt][nt][0], acc[mt][nt][1]);
            *(float2*)(g_y + (size_t)(r0 + 8) * OF + c0) =
                make_float2(acc[mt][nt][2], acc[mt][nt][3]);
        }
    }
}

// ---------------------------------------------------------------------------
// Kernel 4: out = fwht(g_y)/64 * SV + bias
// ---------------------------------------------------------------------------
__global__ __launch_bounds__(256) void fwht_out_kernel(
        const float* __restrict__ SV, const float* __restrict__ bias,
        float* __restrict__ out) {
    __shared__ float s[4096];
    const int row = blockIdx.x;
    const int tid = threadIdx.x;

    float v[16];
    const float4* ip = (const float4*)(g_y + (size_t)row * OF + tid * 16);
    #pragma unroll
    for (int q = 0; q < 4; q++) {
        float4 a = ip[q];
        v[q*4+0] = a.x; v[q*4+1] = a.y; v[q*4+2] = a.z; v[q*4+3] = a.w;
    }

    fwht4096(v, s, tid);

    float* dst = out + (size_t)row * OF + tid;
    #pragma unroll
    for (int r = 0; r < 16; r++) {
        int c = r * 256 + tid;
        dst[r * 256] = v[r] * 0.015625f * SV[c] + bias[c];
    }
}

// ---------------------------------------------------------------------------
extern "C" void kernel_launch(void* const* d_in, const int* in_sizes, int n_in,
                              void* d_out, int out_size) {
    const float* input  = (const float*)d_in[0];
    const float* SU     = (const float*)d_in[1];
    const float* SV     = (const float*)d_in[2];
    const float* cb     = (const float*)d_in[3];
    const int*   Qidxs  = (const int*)d_in[4];
    const float* Wscale = (const float*)d_in[5];
    const float* bias   = (const float*)d_in[6];
    float* out = (float*)d_out;

    cudaFuncSetAttribute(gemm_f16_kernel,
                         cudaFuncAttributeMaxDynamicSharedMemorySize, GEMM_SMEM);

    fwht_in_kernel<<<TKN, 256>>>(input, SU, Wscale);
    dequant_kernel<<<(OF * (NF / 4)) / 256, 256>>>(cb, Qidxs);
    gemm_f16_kernel<<<dim3(OF / BN, TKN / BM), 256, GEMM_SMEM>>>();
    fwht_out_kernel<<<TKN, 256>>>(SV, bias, out);
}

// round 7
// speedup vs baseline: 2.5602x; 1.0760x over previous
#include <cuda_runtime.h>
#include <cuda_fp16.h>
#include <cstdint>

#define TKN 8192   // tokens = 4*2048
#define NF  4096   // in features
#define OF  4096   // out features

// Scratch (static device globals -- allocation-free per harness rules)
__device__ __half g_x[(size_t)TKN * NF];    // 64 MB: fwht(input*SU)*scale, fp16
__device__ __half g_w[(size_t)OF * NF];     // 32 MB: W, then W' = H*W, fp16
__device__ __half g_tmp[(size_t)OF * NF];   // 32 MB: W-FWHT intermediate

// ---------------------------------------------------------------------------
// Register/shuffle FWHT core: 256 threads, 16 elements/thread, N=4096.
// ---------------------------------------------------------------------------
__device__ __forceinline__ void fwht4096(float* v, float* s, int tid) {
    const int lane = tid & 31;
    #pragma unroll
    for (int h = 1; h < 16; h <<= 1)
        #pragma unroll
        for (int i = 0; i < 16; i++)
            if (!(i & h)) {
                float a = v[i], b = v[i ^ h];
                v[i] = a + b; v[i ^ h] = a - b;
            }
    #pragma unroll
    for (int d = 1; d < 32; d <<= 1) {
        #pragma unroll
        for (int r = 0; r < 16; r++) {
            float o = __shfl_xor_sync(0xffffffffu, v[r], d);
            v[r] = (lane & d) ? (o - v[r]) : (v[r] + o);
        }
    }
    float4* sv = (float4*)(s + tid * 16);
    sv[0] = make_float4(v[0], v[1], v[2], v[3]);
    sv[1] = make_float4(v[4], v[5], v[6], v[7]);
    sv[2] = make_float4(v[8], v[9], v[10], v[11]);
    sv[3] = make_float4(v[12], v[13], v[14], v[15]);
    __syncthreads();
    #pragma unroll
    for (int r = 0; r < 16; r++) v[r] = s[r * 256 + tid];
    #pragma unroll
    for (int h = 2; h < 16; h <<= 1)
        #pragma unroll
        for (int i = 0; i < 16; i++)
            if (!(i & h)) {
                float a = v[i], b = v[i ^ h];
                v[i] = a + b; v[i ^ h] = a - b;
            }
}

// ---------------------------------------------------------------------------
// Kernel 1: g_x = fp16( fwht(input * SU) * Wscale/64 )
// ---------------------------------------------------------------------------
__global__ __launch_bounds__(256) void fwht_in_kernel(
        const float* __restrict__ in, const float* __restrict__ SU,
        const float* __restrict__ wscale) {
    __shared__ float s[4096];
    const int row = blockIdx.x;
    const int tid = threadIdx.x;

    float v[16];
    const float4* ip = (const float4*)(in + (size_t)row * NF + tid * 16);
    const float4* up = (const float4*)(SU + tid * 16);
    #pragma unroll
    for (int q = 0; q < 4; q++) {
        float4 a = ip[q], b = up[q];
        v[q*4+0] = a.x*b.x; v[q*4+1] = a.y*b.y;
        v[q*4+2] = a.z*b.z; v[q*4+3] = a.w*b.w;
    }

    fwht4096(v, s, tid);

    const float sc = wscale[0] * 0.015625f;   // Wscale / sqrt(4096)
    __half* dst = g_x + (size_t)row * NF + tid;
    #pragma unroll
    for (int r = 0; r < 16; r++)
        dst[r * 256] = __float2half_rn(v[r] * sc);
}

// ---------------------------------------------------------------------------
// Kernel 2: dequantize W -> fp16
// ---------------------------------------------------------------------------
__global__ __launch_bounds__(256) void dequant_kernel(
        const float* __restrict__ cb, const int* __restrict__ qidx) {
    int idx = blockIdx.x * 256 + threadIdx.x;   // 0 .. OF*NF/4-1
    int q = __ldg(qidx + idx);
    float4 v = __ldg((const float4*)cb + q);
    __half2 a = __floats2half2_rn(v.x, v.y);
    __half2 b = __floats2half2_rn(v.z, v.w);
    uint2 o;
    o.x = *reinterpret_cast<uint32_t*>(&a);
    o.y = *reinterpret_cast<uint32_t*>(&b);
    ((uint2*)g_w)[idx] = o;
}

// ---------------------------------------------------------------------------
// Kernel 2b: FWHT of W along the OUTPUT dim (o), 64-point per pass.
// pass 0: src=g_w,  dst=g_tmp, o = b*64 + r  -> transforms bits 0..5 of o
// pass 1: src=g_tmp, dst=g_w,  o = b + 64*r  -> transforms bits 6..11 of o
// NOTE: globals are referenced IN DEVICE CODE (passing a __device__ symbol as
// a kernel argument from host code is UB and was the R6 failure).
// ---------------------------------------------------------------------------
__global__ __launch_bounds__(256) void wfwht_kernel(int pass) {
    const __half2* s2 = (const __half2*)(pass == 0 ? g_w : g_tmp);
    __half2*       d2 = (__half2*)(pass == 0 ? g_tmp : g_w);
    const size_t row0  = (pass == 0) ? (size_t)blockIdx.x * 64 : (size_t)blockIdx.x;
    const size_t rstep = (pass == 0) ? (size_t)(NF / 2) : (size_t)64 * (NF / 2);
    const size_t col = (size_t)blockIdx.y * 256 + threadIdx.x;   // half2 col
    const size_t base = row0 * (NF / 2) + col;

    float2 v[64];
    #pragma unroll
    for (int r = 0; r < 64; r++)
        v[r] = __half22float2(s2[base + r * rstep]);

    #pragma unroll
    for (int h = 1; h < 64; h <<= 1)
        #pragma unroll
        for (int i = 0; i < 64; i++)
            if (!(i & h)) {
                float2 a = v[i], c = v[i ^ h];
                v[i].x = a.x + c.x;     v[i].y = a.y + c.y;
                v[i ^ h].x = a.x - c.x; v[i ^ h].y = a.y - c.y;
            }

    #pragma unroll
    for (int r = 0; r < 64; r++)
        d2[base + r * rstep] = __float22half2_rn(v[r]);
}

// ---------------------------------------------------------------------------
// Kernel 3: fp16 mma.sync GEMM + fused epilogue
//   out[t][o] = (sum_i g_x[t][i] * g_w[o][i]) * (1/64) * SV[o] + bias[o]
// BM=256 BN=128 BKH=128, 8 warps of 64x64, ldmatrix + fragment
// double-buffering, 2-stage cp.async pipeline (96KB/stage).
// ---------------------------------------------------------------------------
#define BM 256
#define BN 128
#define BKH 128                      // halves per k-stage (256 bytes, 2 sub-tiles)
#define KITERS (NF / BKH)            // 32
#define A_HALF_B (BM * 128)          // 32768
#define B_HALF_B (BN * 128)          // 16384
#define A_TILE_B (2 * A_HALF_B)      // 65536
#define B_TILE_B (2 * B_HALF_B)      // 32768
#define STAGE_B  (A_TILE_B + B_TILE_B)      // 98304
#define GEMM_SMEM (2 * STAGE_B)             // 196608

__device__ __forceinline__ uint32_t sw128(uint32_t o) { return o ^ ((o >> 3) & 0x70); }

__device__ __forceinline__ void cpa(uint32_t dst, const void* src) {
    asm volatile("cp.async.cg.shared.global [%0], [%1], 16;" :: "r"(dst), "l"(src));
}

__device__ __forceinline__ void ldsm4(uint32_t* r, uint32_t addr) {
    asm volatile("ldmatrix.sync.aligned.m8n8.x4.shared.b16 {%0,%1,%2,%3}, [%4];"
                 : "=r"(r[0]), "=r"(r[1]), "=r"(r[2]), "=r"(r[3]) : "r"(addr));
}

__device__ __forceinline__ void load_stage(uint32_t base, int st, int mBase,
                                           int nBase, int tid) {
    const int k0 = st * BKH;
    const __half* A = g_x + (size_t)mBase * NF + k0;
    const __half* B = g_w + (size_t)nBase * NF + k0;
    #pragma unroll
    for (int i = 0; i < 16; i++) {                // A: 4096 x 16B
        int id = tid + (i << 8);
        int r = id >> 4, c16 = id & 15;
        cpa(base + (c16 >> 3) * A_HALF_B + sw128(r * 128 + (c16 & 7) * 16),
            A + (size_t)r * NF + c16 * 8);
    }
    #pragma unroll
    for (int i = 0; i < 8; i++) {                 // B: 2048 x 16B
        int id = tid + (i << 8);
        int r = id >> 4, c16 = id & 15;
        cpa(base + A_TILE_B + (c16 >> 3) * B_HALF_B + sw128(r * 128 + (c16 & 7) * 16),
            B + (size_t)r * NF + c16 * 8);
    }
    asm volatile("cp.async.commit_group;");
}

__global__ __launch_bounds__(256, 1) void gemm_f16_kernel(
        const float* __restrict__ SV, const float* __restrict__ bias,
        float* __restrict__ out) {
    extern __shared__ __align__(1024) uint8_t sm[];
    const uint32_t smem_base = (uint32_t)__cvta_generic_to_shared(sm);

    const int tid  = threadIdx.x;
    const int warp = tid >> 5, lane = tid & 31;
    const int wm = warp >> 1, wn = warp & 1;       // 4 x 2 warp grid, 64x64 tiles
    const int g  = lane >> 2, t = lane & 3;
    const int mBase = blockIdx.y * BM;
    const int nBase = blockIdx.x * BN;

    // ldmatrix lane addressing
    const int a_row  = lane & 15;
    const int a_koff = (lane >> 4) * 16;           // 0/16 bytes
    const int b_row  = (lane & 7) + ((lane >> 4) & 1) * 8;
    const int b_koff = ((lane >> 3) & 1) * 16;

    uint32_t aBase[4], aXor[4], bBase[4], bXor[4];
    #pragma unroll
    for (int mt = 0; mt < 4; mt++) {
        uint32_t rb = (wm * 64 + mt * 16 + a_row) * 128;
        aBase[mt] = rb; aXor[mt] = (rb >> 3) & 0x70;
    }
    #pragma unroll
    for (int np = 0; np < 4; np++) {
        uint32_t rb = (wn * 64 + np * 16 + b_row) * 128;
        bBase[np] = rb; bXor[np] = (rb >> 3) & 0x70;
    }

    float acc[4][8][4];
    #pragma unroll
    for (int a = 0; a < 4; a++)
        #pragma unroll
        for (int b = 0; b < 8; b++)
            #pragma unroll
            for (int c = 0; c < 4; c++) acc[a][b][c] = 0.f;

    load_stage(smem_base, 0, mBase, nBase, tid);

    for (int s = 0; s < KITERS; s++) {
        asm volatile("cp.async.wait_group 0;" ::: "memory");
        __syncthreads();
        if (s + 1 < KITERS)
            load_stage(smem_base + ((s + 1) & 1) * STAGE_B, s + 1,
                       mBase, nBase, tid);

        const uint32_t As = smem_base + (s & 1) * STAGE_B;
        const uint32_t Bs = As + A_TILE_B;

        uint32_t af[2][4][4], bf[2][4][4];
        #pragma unroll
        for (int mt = 0; mt < 4; mt++)
            ldsm4(af[0][mt], As + aBase[mt] + (a_koff ^ aXor[mt]));
        #pragma unroll
        for (int np = 0; np < 4; np++)
            ldsm4(bf[0][np], Bs + bBase[np] + (b_koff ^ bXor[np]));

        #pragma unroll
        for (int kc = 0; kc < 8; kc++) {           // 8 k-chunks of 16
            const int cur = kc & 1, nxt = cur ^ 1;
            if (kc < 7) {
                const int kn = kc + 1;
                const uint32_t ah = As + (kn >> 2) * A_HALF_B;
                const uint32_t bh = Bs + (kn >> 2) * B_HALF_B;
                const uint32_t ak = (kn & 3) * 32 + a_koff;
                const uint32_t bk = (kn & 3) * 32 + b_koff;
                #pragma unroll
                for (int mt = 0; mt < 4; mt++)
                    ldsm4(af[nxt][mt], ah + aBase[mt] + (ak ^ aXor[mt]));
                #pragma unroll
                for (int np = 0; np < 4; np++)
                    ldsm4(bf[nxt][np], bh + bBase[np] + (bk ^ bXor[np]));
            }
            #pragma unroll
            for (int mt = 0; mt < 4; mt++)
                #pragma unroll
                for (int nt = 0; nt < 8; nt++) {
                    float* c = acc[mt][nt];
                    const uint32_t b0 = bf[cur][nt >> 1][(nt & 1) * 2 + 0];
                    const uint32_t b1 = bf[cur][nt >> 1][(nt & 1) * 2 + 1];
                    asm volatile(
                        "mma.sync.aligned.m16n8k16.row.col.f32.f16.f16.f32 "
                        "{%0,%1,%2,%3}, {%4,%5,%6,%7}, {%8,%9}, {%0,%1,%2,%3};"
                        : "+f"(c[0]), "+f"(c[1]), "+f"(c[2]), "+f"(c[3])
                        : "r"(af[cur][mt][0]), "r"(af[cur][mt][1]),
                          "r"(af[cur][mt][2]), "r"(af[cur][mt][3]),
                          "r"(b0), "r"(b1));
                }
        }
        // no bottom barrier: top barrier of next iter orders compute(s)
        // before the cp.async overwrite of buffer s&1 (issued at iter s+1).
    }

    // Fused epilogue: out = acc/64 * SV + bias
    const float isq = 0.015625f;   // 1/sqrt(4096)
    #pragma unroll
    for (int nt = 0; nt < 8; nt++) {
        const int c0 = nBase + wn * 64 + nt * 8 + (t << 1);
        const float sv0 = __ldg(SV + c0)     * isq;
        const float sv1 = __ldg(SV + c0 + 1) * isq;
        const float bb0 = __ldg(bias + c0);
        const float bb1 = __ldg(bias + c0 + 1);
        #pragma unroll
        for (int mt = 0; mt < 4; mt++) {
            const int r0 = mBase + wm * 64 + mt * 16 + g;
            float* c = acc[mt][nt];
            *(float2*)(out + (size_t)r0 * OF + c0) =
                make_float2(c[0] * sv0 + bb0, c[1] * sv1 + bb1);
            *(float2*)(out + (size_t)(r0 + 8) * OF + c0) =
                make_float2(c[2] * sv0 + bb0, c[3] * sv1 + bb1);
        }
    }
}

// ---------------------------------------------------------------------------
extern "C" void kernel_launch(void* const* d_in, const int* in_sizes, int n_in,
                              void* d_out, int out_size) {
    const float* input  = (const float*)d_in[0];
    const float* SU     = (const float*)d_in[1];
    const float* SV     = (const float*)d_in[2];
    const float* cb     = (const float*)d_in[3];
    const int*   Qidxs  = (const int*)d_in[4];
    const float* Wscale = (const float*)d_in[5];
    const float* bias   = (const float*)d_in[6];
    float* out = (float*)d_out;

    cudaFuncSetAttribute(gemm_f16_kernel,
                         cudaFuncAttributeMaxDynamicSharedMemorySize, GEMM_SMEM);

    fwht_in_kernel<<<TKN, 256>>>(input, SU, Wscale);
    dequant_kernel<<<(OF * (NF / 4)) / 256, 256>>>(cb, Qidxs);
    // W' = H * W  (FWHT along output dim, two 64-point passes)
    wfwht_kernel<<<dim3(64, NF / 512), 256>>>(0);
    wfwht_kernel<<<dim3(64, NF / 512), 256>>>(1);
    gemm_f16_kernel<<<dim3(OF / BN, TKN / BM), 256, GEMM_SMEM>>>(SV, bias, out);
}

// round 8
// speedup vs baseline: 2.6032x; 1.0168x over previous
#include <cuda_runtime.h>
#include <cuda_fp16.h>
#include <cstdint>

#define TKN 8192   // tokens = 4*2048
#define NF  4096   // in features
#define OF  4096   // out features

// Scratch (static device globals -- allocation-free per harness rules)
__device__ __half g_x[(size_t)TKN * NF];    // 64 MB: fwht(input*SU)*scale, fp16
__device__ __half g_w[(size_t)OF * NF];     // 32 MB: W' = H*W, fp16
__device__ __half g_tmp[(size_t)OF * NF];   // 32 MB: W-FWHT intermediate

// ---------------------------------------------------------------------------
// Kernel 1: g_x = fp16( fwht(input * SU) * Wscale/64 )
// 256 threads, 16 elems/thread. Two register views (8 bits in regs) so only
// 4 shuffle stages are needed:
//   view1 (i = tid*16 + r): reg stages b0-3, shfl d=1,2,4,8 -> b4-7
//   transpose via smem, view2 (i = r*256 + tid): reg stages b8-11
// ---------------------------------------------------------------------------
__global__ __launch_bounds__(256) void fwht_in_kernel(
        const float* __restrict__ in, const float* __restrict__ SU,
        const float* __restrict__ wscale) {
    __shared__ float s[4096];
    const int row = blockIdx.x;
    const int tid = threadIdx.x;
    const int lane = tid & 31;

    float v[16];
    const float4* ip = (const float4*)(in + (size_t)row * NF + tid * 16);
    const float4* up = (const float4*)(SU + tid * 16);
    #pragma unroll
    for (int q = 0; q < 4; q++) {
        float4 a = ip[q], b = up[q];
        v[q*4+0] = a.x*b.x; v[q*4+1] = a.y*b.y;
        v[q*4+2] = a.z*b.z; v[q*4+3] = a.w*b.w;
    }

    // view1 reg stages: bits b0-3
    #pragma unroll
    for (int h = 1; h < 16; h <<= 1)
        #pragma unroll
        for (int i = 0; i < 16; i++)
            if (!(i & h)) {
                float a = v[i], b = v[i ^ h];
                v[i] = a + b; v[i ^ h] = a - b;
            }
    // shfl stages: bits b4-7 (lane bits 0-3)
    #pragma unroll
    for (int d = 1; d < 16; d <<= 1) {
        #pragma unroll
        for (int r = 0; r < 16; r++) {
            float o = __shfl_xor_sync(0xffffffffu, v[r], d);
            v[r] = (lane & d) ? (o - v[r]) : (v[r] + o);
        }
    }
    // transpose: write i = tid*16 + r, read i = r*256 + tid
    float4* sv = (float4*)(s + tid * 16);
    sv[0] = make_float4(v[0], v[1], v[2], v[3]);
    sv[1] = make_float4(v[4], v[5], v[6], v[7]);
    sv[2] = make_float4(v[8], v[9], v[10], v[11]);
    sv[3] = make_float4(v[12], v[13], v[14], v[15]);
    __syncthreads();
    #pragma unroll
    for (int r = 0; r < 16; r++) v[r] = s[r * 256 + tid];
    // view2 reg stages: bits b8-11 (r bits 0-3)
    #pragma unroll
    for (int h = 1; h < 16; h <<= 1)
        #pragma unroll
        for (int i = 0; i < 16; i++)
            if (!(i & h)) {
                float a = v[i], b = v[i ^ h];
                v[i] = a + b; v[i ^ h] = a - b;
            }

    const float sc = wscale[0] * 0.015625f;   // Wscale / sqrt(4096)
    __half* dst = g_x + (size_t)row * NF + tid;
    #pragma unroll
    for (int r = 0; r < 16; r++)
        dst[r * 256] = __float2half_rn(v[r] * sc);
}

// ---------------------------------------------------------------------------
// Kernel 2: fused dequant + FWHT pass 0 over output-dim bits 0..5.
// Block (b, by): o-rows [b*64, b*64+64), half2 cols [by*256, by*256+256).
// Gathers W[o][i] = cb[Qidxs[o][i/4]][i%4] from smem-resident cb, does the
// 64-point butterfly in fp32 registers, writes g_tmp (fp16).
// ---------------------------------------------------------------------------
__global__ __launch_bounds__(256) void wfwht0_kernel(
        const float* __restrict__ cb, const int* __restrict__ qidx) {
    __shared__ float2 scb[512];               // cb: 256 codes x 2 float2
    const int tid = threadIdx.x;
    ((float4*)scb)[tid] = ((const float4*)cb)[tid];   // 256 x 16B = 4KB
    __syncthreads();

    const int b = blockIdx.x;                 // 0..63
    const int col = blockIdx.y * 256 + tid;   // half2 col, 0..2047
    const int qcol = col >> 1;                // code col, 0..1023
    const int sub  = col & 1;                 // which float2 of the code
    const int* qrow = qidx + (size_t)b * 64 * (NF / 4) + qcol;

    float2 v[64];
    #pragma unroll
    for (int r = 0; r < 64; r++) {
        int q = __ldg(qrow + (size_t)r * (NF / 4));
        v[r] = scb[q * 2 + sub];
    }

    #pragma unroll
    for (int h = 1; h < 64; h <<= 1)
        #pragma unroll
        for (int i = 0; i < 64; i++)
            if (!(i & h)) {
                float2 a = v[i], c = v[i ^ h];
                v[i].x = a.x + c.x;     v[i].y = a.y + c.y;
                v[i ^ h].x = a.x - c.x; v[i ^ h].y = a.y - c.y;
            }

    __half2* d2 = (__half2*)g_tmp;
    const size_t base = (size_t)b * 64 * (NF / 2) + col;
    #pragma unroll
    for (int r = 0; r < 64; r++)
        d2[base + (size_t)r * (NF / 2)] = __float22half2_rn(v[r]);
}

// ---------------------------------------------------------------------------
// Kernel 2b: FWHT pass 1 over output-dim bits 6..11 (rows o = b + 64*r).
// Reads g_tmp, writes g_w.
// ---------------------------------------------------------------------------
__global__ __launch_bounds__(256) void wfwht1_kernel() {
    const __half2* s2 = (const __half2*)g_tmp;
    __half2*       d2 = (__half2*)g_w;
    const size_t col  = (size_t)blockIdx.y * 256 + threadIdx.x;
    const size_t base = (size_t)blockIdx.x * (NF / 2) + col;
    const size_t rstep = (size_t)64 * (NF / 2);

    float2 v[64];
    #pragma unroll
    for (int r = 0; r < 64; r++)
        v[r] = __half22float2(s2[base + r * rstep]);

    #pragma unroll
    for (int h = 1; h < 64; h <<= 1)
        #pragma unroll
        for (int i = 0; i < 64; i++)
            if (!(i & h)) {
                float2 a = v[i], c = v[i ^ h];
                v[i].x = a.x + c.x;     v[i].y = a.y + c.y;
                v[i ^ h].x = a.x - c.x; v[i ^ h].y = a.y - c.y;
            }

    #pragma unroll
    for (int r = 0; r < 64; r++)
        d2[base + r * rstep] = __float22half2_rn(v[r]);
}

// ---------------------------------------------------------------------------
// Kernel 3: fp16 mma.sync GEMM + fused epilogue
//   out[t][o] = (sum_i g_x[t][i] * g_w[o][i]) * (1/64) * SV[o] + bias[o]
// BM=256 BN=128 BKH=128, 8 warps of 64x64, ldmatrix + fragment
// double-buffering, 2-stage cp.async pipeline (96KB/stage).
// ---------------------------------------------------------------------------
#define BM 256
#define BN 128
#define BKH 128                      // halves per k-stage (256 bytes, 2 sub-tiles)
#define KITERS (NF / BKH)            // 32
#define A_HALF_B (BM * 128)          // 32768
#define B_HALF_B (BN * 128)          // 16384
#define A_TILE_B (2 * A_HALF_B)      // 65536
#define B_TILE_B (2 * B_HALF_B)      // 32768
#define STAGE_B  (A_TILE_B + B_TILE_B)      // 98304
#define GEMM_SMEM (2 * STAGE_B)             // 196608

__device__ __forceinline__ uint32_t sw128(uint32_t o) { return o ^ ((o >> 3) & 0x70); }

__device__ __forceinline__ void cpa(uint32_t dst, const void* src) {
    asm volatile("cp.async.cg.shared.global [%0], [%1], 16;" :: "r"(dst), "l"(src));
}

__device__ __forceinline__ void ldsm4(uint32_t* r, uint32_t addr) {
    asm volatile("ldmatrix.sync.aligned.m8n8.x4.shared.b16 {%0,%1,%2,%3}, [%4];"
                 : "=r"(r[0]), "=r"(r[1]), "=r"(r[2]), "=r"(r[3]) : "r"(addr));
}

__device__ __forceinline__ void load_stage(uint32_t base, int st, int mBase,
                                           int nBase, int tid) {
    const int k0 = st * BKH;
    const __half* A = g_x + (size_t)mBase * NF + k0;
    const __half* B = g_w + (size_t)nBase * NF + k0;
    #pragma unroll
    for (int i = 0; i < 16; i++) {                // A: 4096 x 16B
        int id = tid + (i << 8);
        int r = id >> 4, c16 = id & 15;
        cpa(base + (c16 >> 3) * A_HALF_B + sw128(r * 128 + (c16 & 7) * 16),
            A + (size_t)r * NF + c16 * 8);
    }
    #pragma unroll
    for (int i = 0; i < 8; i++) {                 // B: 2048 x 16B
        int id = tid + (i << 8);
        int r = id >> 4, c16 = id & 15;
        cpa(base + A_TILE_B + (c16 >> 3) * B_HALF_B + sw128(r * 128 + (c16 & 7) * 16),
            B + (size_t)r * NF + c16 * 8);
    }
    asm volatile("cp.async.commit_group;");
}

__global__ __launch_bounds__(256, 1) void gemm_f16_kernel(
        const float* __restrict__ SV, const float* __restrict__ bias,
        float* __restrict__ out) {
    extern __shared__ __align__(1024) uint8_t sm[];
    const uint32_t smem_base = (uint32_t)__cvta_generic_to_shared(sm);

    const int tid  = threadIdx.x;
    const int warp = tid >> 5, lane = tid & 31;
    const int wm = warp >> 1, wn = warp & 1;       // 4 x 2 warp grid, 64x64 tiles
    const int g  = lane >> 2, t = lane & 3;
    const int mBase = blockIdx.y * BM;
    const int nBase = blockIdx.x * BN;

    // ldmatrix lane addressing
    const int a_row  = lane & 15;
    const int a_koff = (lane >> 4) * 16;           // 0/16 bytes
    const int b_row  = (lane & 7) + ((lane >> 4) & 1) * 8;
    const int b_koff = ((lane >> 3) & 1) * 16;

    uint32_t aBase[4], aXor[4], bBase[4], bXor[4];
    #pragma unroll
    for (int mt = 0; mt < 4; mt++) {
        uint32_t rb = (wm * 64 + mt * 16 + a_row) * 128;
        aBase[mt] = rb; aXor[mt] = (rb >> 3) & 0x70;
    }
    #pragma unroll
    for (int np = 0; np < 4; np++) {
        uint32_t rb = (wn * 64 + np * 16 + b_row) * 128;
        bBase[np] = rb; bXor[np] = (rb >> 3) & 0x70;
    }

    float acc[4][8][4];
    #pragma unroll
    for (int a = 0; a < 4; a++)
        #pragma unroll
        for (int b = 0; b < 8; b++)
            #pragma unroll
            for (int c = 0; c < 4; c++) acc[a][b][c] = 0.f;

    load_stage(smem_base, 0, mBase, nBase, tid);

    for (int s = 0; s < KITERS; s++) {
        asm volatile("cp.async.wait_group 0;" ::: "memory");
        __syncthreads();
        if (s + 1 < KITERS)
            load_stage(smem_base + ((s + 1) & 1) * STAGE_B, s + 1,
                       mBase, nBase, tid);

        const uint32_t As = smem_base + (s & 1) * STAGE_B;
        const uint32_t Bs = As + A_TILE_B;

        uint32_t af[2][4][4], bf[2][4][4];
        #pragma unroll
        for (int mt = 0; mt < 4; mt++)
            ldsm4(af[0][mt], As + aBase[mt] + (a_koff ^ aXor[mt]));
        #pragma unroll
        for (int np = 0; np < 4; np++)
            ldsm4(bf[0][np], Bs + bBase[np] + (b_koff ^ bXor[np]));

        #pragma unroll
        for (int kc = 0; kc < 8; kc++) {           // 8 k-chunks of 16
            const int cur = kc & 1, nxt = cur ^ 1;
            if (kc < 7) {
                const int kn = kc + 1;
                const uint32_t ah = As + (kn >> 2) * A_HALF_B;
                const uint32_t bh = Bs + (kn >> 2) * B_HALF_B;
                const uint32_t ak = (kn & 3) * 32 + a_koff;
                const uint32_t bk = (kn & 3) * 32 + b_koff;
                #pragma unroll
                for (int mt = 0; mt < 4; mt++)
                    ldsm4(af[nxt][mt], ah + aBase[mt] + (ak ^ aXor[mt]));
                #pragma unroll
                for (int np = 0; np < 4; np++)
                    ldsm4(bf[nxt][np], bh + bBase[np] + (bk ^ bXor[np]));
            }
            #pragma unroll
            for (int mt = 0; mt < 4; mt++)
                #pragma unroll
                for (int nt = 0; nt < 8; nt++) {
                    float* c = acc[mt][nt];
                    const uint32_t b0 = bf[cur][nt >> 1][(nt & 1) * 2 + 0];
                    const uint32_t b1 = bf[cur][nt >> 1][(nt & 1) * 2 + 1];
                    asm volatile(
                        "mma.sync.aligned.m16n8k16.row.col.f32.f16.f16.f32 "
                        "{%0,%1,%2,%3}, {%4,%5,%6,%7}, {%8,%9}, {%0,%1,%2,%3};"
                        : "+f"(c[0]), "+f"(c[1]), "+f"(c[2]), "+f"(c[3])
                        : "r"(af[cur][mt][0]), "r"(af[cur][mt][1]),
                          "r"(af[cur][mt][2]), "r"(af[cur][mt][3]),
                          "r"(b0), "r"(b1));
                }
        }
        // no bottom barrier: top barrier of next iter orders compute(s)
        // before the cp.async overwrite of buffer s&1 (issued at iter s+1).
    }

    // Fused epilogue: out = acc/64 * SV + bias
    const float isq = 0.015625f;   // 1/sqrt(4096)
    #pragma unroll
    for (int nt = 0; nt < 8; nt++) {
        const int c0 = nBase + wn * 64 + nt * 8 + (t << 1);
        const float sv0 = __ldg(SV + c0)     * isq;
        const float sv1 = __ldg(SV + c0 + 1) * isq;
        const float bb0 = __ldg(bias + c0);
        const float bb1 = __ldg(bias + c0 + 1);
        #pragma unroll
        for (int mt = 0; mt < 4; mt++) {
            const int r0 = mBase + wm * 64 + mt * 16 + g;
            float* c = acc[mt][nt];
            *(float2*)(out + (size_t)r0 * OF + c0) =
                make_float2(c[0] * sv0 + bb0, c[1] * sv1 + bb1);
            *(float2*)(out + (size_t)(r0 + 8) * OF + c0) =
                make_float2(c[2] * sv0 + bb0, c[3] * sv1 + bb1);
        }
    }
}

// ---------------------------------------------------------------------------
extern "C" void kernel_launch(void* const* d_in, const int* in_sizes, int n_in,
                              void* d_out, int out_size) {
    const float* input  = (const float*)d_in[0];
    const float* SU     = (const float*)d_in[1];
    const float* SV     = (const float*)d_in[2];
    const float* cb     = (const float*)d_in[3];
    const int*   Qidxs  = (const int*)d_in[4];
    const float* Wscale = (const float*)d_in[5];
    const float* bias   = (const float*)d_in[6];
    float* out = (float*)d_out;

    cudaFuncSetAttribute(gemm_f16_kernel,
                         cudaFuncAttributeMaxDynamicSharedMemorySize, GEMM_SMEM);

    fwht_in_kernel<<<TKN, 256>>>(input, SU, Wscale);
    // W' = H * W  (FWHT along output dim; pass 0 fused with codebook dequant)
    wfwht0_kernel<<<dim3(64, NF / 512), 256>>>(cb, Qidxs);
    wfwht1_kernel<<<dim3(64, NF / 512), 256>>>();
    gemm_f16_kernel<<<dim3(OF / BN, TKN / BM), 256, GEMM_SMEM>>>(SV, bias, out);
}